// round 2
// baseline (speedup 1.0000x reference)
#include <cuda_runtime.h>

#define BB   4
#define CC   256
#define HH   64
#define WW   64
#define HWS  4096         // H*W
#define NP   9            // kernel points
#define OCH  18           // offset channels
#define OPL  256          // out planes

#define MT   128          // GEMM M tile (positions per block)
#define CCK  4            // channels per K chunk
#define KC   36           // K per chunk = CCK*9
#define NTH  512
#define SB_STRIDE 260     // padded B row stride (floats), 16B aligned, conflict-free frag loads

// sampling metadata scratch: per (b,h,w,k): 4 bilinear weights + 4 flat gather indices
__device__ float4 g_mw[BB * HWS * NP];
__device__ int4   g_mi[BB * HWS * NP];

// ---------------------------------------------------------------------------
// Kernel 1: offset conv (3x3, pad 1, C=256 -> 18) + sampling metadata
// one thread per spatial position; w_p staged via smem in 32-channel chunks
// ---------------------------------------------------------------------------
__global__ __launch_bounds__(128) void offsets_kernel(const float* __restrict__ x,
                                                      const float* __restrict__ w_p)
{
    __shared__ float s_wp[32][OCH][12];   // taps padded 9->12 for aligned float4 reads

    const int tid = threadIdx.x;
    const int pos = blockIdx.x * 128 + tid;
    const int b = pos >> 12;
    const int h = (pos >> 6) & 63;
    const int w = pos & 63;

    float acc[OCH];
#pragma unroll
    for (int i = 0; i < OCH; i++) acc[i] = 0.f;

    const float* xb = x + (size_t)b * CC * HWS;

    for (int c0 = 0; c0 < CC; c0 += 32) {
        __syncthreads();
        for (int i = tid; i < 32 * OCH * 9; i += 128) {
            int cl = i / (OCH * 9);
            int r  = i % (OCH * 9);
            int o  = r / 9;
            int t  = r % 9;
            s_wp[cl][o][t] = w_p[(o * CC + c0 + cl) * 9 + t];
        }
        __syncthreads();

        for (int cl = 0; cl < 32; cl++) {
            const float* xp = xb + (c0 + cl) * HWS;
            float xv[9];
#pragma unroll
            for (int dh = -1; dh <= 1; dh++) {
#pragma unroll
                for (int dw = -1; dw <= 1; dw++) {
                    int hh = h + dh, ww = w + dw;
                    float v = 0.f;
                    if (hh >= 0 && hh < HH && ww >= 0 && ww < WW) v = xp[hh * WW + ww];
                    xv[(dh + 1) * 3 + (dw + 1)] = v;
                }
            }
#pragma unroll
            for (int o = 0; o < OCH; o++) {
                float4 wa = *(const float4*)&s_wp[cl][o][0];
                float4 wb = *(const float4*)&s_wp[cl][o][4];
                float  w8 = s_wp[cl][o][8];
                acc[o] += wa.x * xv[0] + wa.y * xv[1] + wa.z * xv[2] + wa.w * xv[3]
                        + wb.x * xv[4] + wb.y * xv[5] + wb.z * xv[6] + wb.w * xv[7]
                        + w8  * xv[8];
            }
        }
    }

    // sampling metadata — exact replica of the reference bilinear formula
#pragma unroll
    for (int k = 0; k < 9; k++) {
        float rx = (float)(k / 3 - 1);
        float ry = (float)(k % 3 - 1);
        float px = acc[k]     + rx + (float)(h + 1);
        float py = acc[9 + k] + ry + (float)(w + 1);
        float fx = floorf(px), fy = floorf(py);
        float ltx = fminf(fmaxf(fx,        0.f), 63.f);
        float lty = fminf(fmaxf(fy,        0.f), 63.f);
        float rbx = fminf(fmaxf(fx + 1.f,  0.f), 63.f);
        float rby = fminf(fmaxf(fy + 1.f,  0.f), 63.f);
        float pxc = fminf(fmaxf(px,        0.f), 63.f);
        float pyc = fminf(fmaxf(py,        0.f), 63.f);
        float glt = (1.f + (ltx - pxc)) * (1.f + (lty - pyc));
        float grb = (1.f - (rbx - pxc)) * (1.f - (rby - pyc));
        float glb = (1.f + (ltx - pxc)) * (1.f - (rby - pyc));
        float grt = (1.f - (rbx - pxc)) * (1.f + (lty - pyc));
        int iltx = (int)ltx, ilty = (int)lty, irbx = (int)rbx, irby = (int)rby;
        g_mw[pos * 9 + k] = make_float4(glt, grb, glb, grt);
        g_mi[pos * 9 + k] = make_int4(iltx * WW + ilty,
                                      irbx * WW + irby,
                                      iltx * WW + irby,
                                      irbx * WW + ilty);
    }
}

// ---------------------------------------------------------------------------
// Kernel 2: implicit gather-GEMM
// out[b,o,h,w] = sum_{c,k} w_conv[o,c,k] * bilinear_sample(x[b,c], meta[b,h,w,k])
// M-tile = 128 positions, N = 256 (full), K chunked by 4 channels (36)
// ---------------------------------------------------------------------------
__global__ __launch_bounds__(NTH, 1) void main_kernel(const float* __restrict__ x,
                                                      const float* __restrict__ wc,
                                                      float* __restrict__ out)
{
    extern __shared__ float smem[];
    float*  sA  = smem;                              // [36][128]           = 4608 f
    float*  sB  = smem + KC * MT;                    // [36][260]           = 9360 f
    float4* sMW = (float4*)(smem + KC * MT + KC * SB_STRIDE);   // [128*9]
    int4*   sMI = (int4*)(sMW + MT * NP);                       // [128*9]

    const int tid = threadIdx.x;
    const int tn  = tid & 15;        // 0..15
    const int tm  = tid >> 4;        // 0..31
    const int p0  = blockIdx.x * MT; // first position of tile (single batch b)
    const int b   = p0 >> 12;
    const float* xb = x + (size_t)b * CC * HWS;

    // load sampling metadata for this tile (reused across all 64 K-chunks)
    for (int i = tid; i < MT * NP; i += NTH) {
        sMW[i] = g_mw[p0 * NP + i];
        sMI[i] = g_mi[p0 * NP + i];
    }

    float acc[4][16];
#pragma unroll
    for (int mi = 0; mi < 4; mi++)
#pragma unroll
        for (int ni = 0; ni < 16; ni++) acc[mi][ni] = 0.f;

    __syncthreads();   // metadata ready

    for (int c0 = 0; c0 < CC; c0 += CCK) {
        // ---- stage A: gather 128 pos x 4 ch x 9 pts bilinear samples ----
        for (int s = tid; s < MT * CCK * NP; s += NTH) {      // 4608
            int posl = s & 127;
            int kk   = s >> 7;          // 0..35 = cl*9 + k
            int cl   = kk / 9;
            int k    = kk - cl * 9;
            float4 wv = sMW[posl * NP + k];
            int4   iv = sMI[posl * NP + k];
            const float* xp = xb + (c0 + cl) * HWS;
            float v = wv.x * xp[iv.x] + wv.y * xp[iv.y]
                    + wv.z * xp[iv.z] + wv.w * xp[iv.w];
            sA[kk * MT + posl] = v;
        }
        // ---- stage B: w_conv chunk [36][256] (contiguous 36-float runs) ----
        for (int i = tid; i < OPL * KC; i += NTH) {           // 9216
            int o  = i / KC;
            int kk = i - o * KC;
            // global addr = o*2304 + c0*9 + kk  (contiguous in kk)
            sB[kk * SB_STRIDE + o] = wc[o * (CC * 9) + c0 * 9 + kk];
        }
        __syncthreads();

        // ---- 128x256x36 FMA block ----
#pragma unroll 6
        for (int kk = 0; kk < KC; kk++) {
            float4 a = *(const float4*)&sA[kk * MT + tm * 4];
            float bf[16];
#pragma unroll
            for (int g = 0; g < 4; g++) {
                float4 bb = *(const float4*)&sB[kk * SB_STRIDE + tn * 4 + g * 64];
                bf[g * 4 + 0] = bb.x; bf[g * 4 + 1] = bb.y;
                bf[g * 4 + 2] = bb.z; bf[g * 4 + 3] = bb.w;
            }
            float av[4] = {a.x, a.y, a.z, a.w};
#pragma unroll
            for (int mi = 0; mi < 4; mi++)
#pragma unroll
                for (int ni = 0; ni < 16; ni++)
                    acc[mi][ni] += av[mi] * bf[ni];
        }
        __syncthreads();
    }

    // ---- epilogue ----
#pragma unroll
    for (int mi = 0; mi < 4; mi++) {
        int p  = p0 + tm * 4 + mi;
        int hw = p & 4095;
#pragma unroll
        for (int g = 0; g < 4; g++) {
#pragma unroll
            for (int j = 0; j < 4; j++) {
                int n = g * 64 + tn * 4 + j;
                out[((size_t)b * OPL + n) * HWS + hw] = acc[mi][g * 4 + j];
            }
        }
    }
}

// ---------------------------------------------------------------------------
extern "C" void kernel_launch(void* const* d_in, const int* in_sizes, int n_in,
                              void* d_out, int out_size)
{
    const float* x      = (const float*)d_in[0];   // (4,256,64,64)
    const float* w_p    = (const float*)d_in[1];   // (18,256,3,3)
    const float* w_conv = (const float*)d_in[2];   // (256,256,3,3)
    float* out = (float*)d_out;                    // (4,256,64,64)

    const int smem2 = (KC * MT + KC * SB_STRIDE + MT * NP * 8) * 4;  // 92,736 B
    cudaFuncSetAttribute(main_kernel, cudaFuncAttributeMaxDynamicSharedMemorySize, smem2);

    offsets_kernel<<<128, 128>>>(x, w_p);
    main_kernel<<<128, NTH, smem2>>>(x, w_conv, out);
}

// round 3
// speedup vs baseline: 1.0545x; 1.0545x over previous
#include <cuda_runtime.h>

#define BB   4
#define CC   256
#define HH   64
#define WW   64
#define HWS  4096         // H*W
#define NP   9            // kernel points
#define OCH  18           // offset channels
#define OPL  256          // out planes
#define KTOT 2304         // C*9

#define MT   64           // GEMM M tile (positions per block) == one image row
#define CCK  4            // channels per K chunk
#define KC   36           // K per chunk = CCK*9
#define NTH  256
#define SB_STRIDE 260     // padded B row stride (floats)

// sampling metadata scratch: per (b,h,w,k): 4 bilinear weights + 4 flat gather indices
__device__ float4 g_mw[BB * HWS * NP];
__device__ int4   g_mi[BB * HWS * NP];
// transposed conv weights: g_wT[kg][o], kg = c*9+k  (2.36 MB, L2-resident)
__device__ float  g_wT[KTOT * OPL];

// ---------------------------------------------------------------------------
// packed fp32 helpers (FFMA2 path — PTX-only)
// ---------------------------------------------------------------------------
__device__ __forceinline__ unsigned long long dup2(float v) {
    unsigned long long r;
    asm("mov.b64 %0, {%1, %1};" : "=l"(r) : "f"(v));
    return r;
}
__device__ __forceinline__ void fma2(unsigned long long& acc,
                                     unsigned long long a, unsigned long long b) {
    asm("fma.rn.f32x2 %0, %1, %2, %0;" : "+l"(acc) : "l"(a), "l"(b));
}
union UPair { unsigned long long u; float2 f; };

// ---------------------------------------------------------------------------
// Kernel 0: transpose w_conv [o][kg] -> g_wT [kg][o]   (one-time, ~5us)
// ---------------------------------------------------------------------------
__global__ __launch_bounds__(256) void transpose_w(const float* __restrict__ wc)
{
    int idx = blockIdx.x * 256 + threadIdx.x;      // over KTOT*OPL
    if (idx < KTOT * OPL) {
        int kg = idx >> 8;
        int o  = idx & 255;
        g_wT[idx] = wc[o * KTOT + kg];
    }
}

// ---------------------------------------------------------------------------
// Kernel 1: offset conv (3x3, pad 1, C=256 -> 18) + sampling metadata
// ---------------------------------------------------------------------------
__global__ __launch_bounds__(128) void offsets_kernel(const float* __restrict__ x,
                                                      const float* __restrict__ w_p)
{
    __shared__ float s_wp[32][OCH][12];

    const int tid = threadIdx.x;
    const int pos = blockIdx.x * 128 + tid;
    const int b = pos >> 12;
    const int h = (pos >> 6) & 63;
    const int w = pos & 63;

    float acc[OCH];
#pragma unroll
    for (int i = 0; i < OCH; i++) acc[i] = 0.f;

    const float* xb = x + (size_t)b * CC * HWS;

    for (int c0 = 0; c0 < CC; c0 += 32) {
        __syncthreads();
        for (int i = tid; i < 32 * OCH * 9; i += 128) {
            int cl = i / (OCH * 9);
            int r  = i % (OCH * 9);
            int o  = r / 9;
            int t  = r % 9;
            s_wp[cl][o][t] = w_p[(o * CC + c0 + cl) * 9 + t];
        }
        __syncthreads();

        for (int cl = 0; cl < 32; cl++) {
            const float* xp = xb + (c0 + cl) * HWS;
            float xv[9];
#pragma unroll
            for (int dh = -1; dh <= 1; dh++) {
#pragma unroll
                for (int dw = -1; dw <= 1; dw++) {
                    int hh = h + dh, ww = w + dw;
                    float v = 0.f;
                    if (hh >= 0 && hh < HH && ww >= 0 && ww < WW) v = xp[hh * WW + ww];
                    xv[(dh + 1) * 3 + (dw + 1)] = v;
                }
            }
#pragma unroll
            for (int o = 0; o < OCH; o++) {
                float4 wa = *(const float4*)&s_wp[cl][o][0];
                float4 wb = *(const float4*)&s_wp[cl][o][4];
                float  w8 = s_wp[cl][o][8];
                acc[o] += wa.x * xv[0] + wa.y * xv[1] + wa.z * xv[2] + wa.w * xv[3]
                        + wb.x * xv[4] + wb.y * xv[5] + wb.z * xv[6] + wb.w * xv[7]
                        + w8  * xv[8];
            }
        }
    }

#pragma unroll
    for (int k = 0; k < 9; k++) {
        float rx = (float)(k / 3 - 1);
        float ry = (float)(k % 3 - 1);
        float px = acc[k]     + rx + (float)(h + 1);
        float py = acc[9 + k] + ry + (float)(w + 1);
        float fx = floorf(px), fy = floorf(py);
        float ltx = fminf(fmaxf(fx,        0.f), 63.f);
        float lty = fminf(fmaxf(fy,        0.f), 63.f);
        float rbx = fminf(fmaxf(fx + 1.f,  0.f), 63.f);
        float rby = fminf(fmaxf(fy + 1.f,  0.f), 63.f);
        float pxc = fminf(fmaxf(px,        0.f), 63.f);
        float pyc = fminf(fmaxf(py,        0.f), 63.f);
        float glt = (1.f + (ltx - pxc)) * (1.f + (lty - pyc));
        float grb = (1.f - (rbx - pxc)) * (1.f - (rby - pyc));
        float glb = (1.f + (ltx - pxc)) * (1.f - (rby - pyc));
        float grt = (1.f - (rbx - pxc)) * (1.f + (lty - pyc));
        int iltx = (int)ltx, ilty = (int)lty, irbx = (int)rbx, irby = (int)rby;
        g_mw[pos * 9 + k] = make_float4(glt, grb, glb, grt);
        g_mi[pos * 9 + k] = make_int4(iltx * WW + ilty,
                                      irbx * WW + irby,
                                      iltx * WW + irby,
                                      irbx * WW + ilty);
    }
}

// ---------------------------------------------------------------------------
// Kernel 2: implicit gather-GEMM, packed-fp32 (FFMA2)
// M tile = 64 positions, N = 256, K chunk = 36 (4 channels)
// 256 threads: thread tile 8m x 8n, acc packed over M-pairs
// 2 CTAs/SM for gather/math overlap
// ---------------------------------------------------------------------------
__global__ void __launch_bounds__(NTH, 2) main_kernel(const float* __restrict__ x,
                                                      float* __restrict__ out)
{
    extern __shared__ float smem[];
    float*  sA  = smem;                                   // [36][64]
    float*  sB  = smem + KC * MT;                         // [36][260]
    float4* sMW = (float4*)(smem + KC * MT + KC * SB_STRIDE);  // [64*9]
    int4*   sMI = (int4*)(sMW + MT * NP);                      // [64*9]

    const int tid = threadIdx.x;
    const int tn4 = (tid & 31) * 4;   // n base within half (0..124)
    const int tm  = tid >> 5;         // 0..7
    const int p0  = blockIdx.x * MT;  // all positions in one batch b, one row h
    const int b   = p0 >> 12;
    const float* xb = x + (size_t)b * CC * HWS;

    // stage metadata for the tile (reused across all 64 K-chunks)
    for (int i = tid; i < MT * NP; i += NTH) {
        sMW[i] = g_mw[p0 * NP + i];
        sMI[i] = g_mi[p0 * NP + i];
    }

    unsigned long long acc_[8][4];    // [n][m-pair], each = f32x2 over 2 consecutive m
#pragma unroll
    for (int n = 0; n < 8; n++)
#pragma unroll
        for (int mp = 0; mp < 4; mp++) acc_[n][mp] = 0ull;

    __syncthreads();

    for (int c0 = 0; c0 < CC; c0 += CCK) {
        // ---- stage A: gather 64 pos x 4 ch x 9 pts bilinear samples ----
        for (int s = tid; s < MT * KC; s += NTH) {        // 2304, 9 per thread
            int posl = s & 63;
            int kk   = s >> 6;            // 0..35
            int cl   = kk / 9;
            int k    = kk - cl * 9;
            float4 wv = sMW[posl * NP + k];
            int4   iv = sMI[posl * NP + k];
            const float* xp = xb + (c0 + cl) * HWS;
            sA[kk * MT + posl] = wv.x * __ldg(xp + iv.x) + wv.y * __ldg(xp + iv.y)
                               + wv.z * __ldg(xp + iv.z) + wv.w * __ldg(xp + iv.w);
        }
        // ---- stage B: copy g_wT rows [c0*9 .. c0*9+36) x [0..256) ----
        for (int i = tid; i < KC * 64; i += NTH) {        // 2304 float4s, 9 per thread
            int kk = i >> 6;
            int o4 = (i & 63) << 2;
            *(float4*)&sB[kk * SB_STRIDE + o4] =
                *(const float4*)&g_wT[(c0 * 9 + kk) * OPL + o4];
        }
        __syncthreads();

        // ---- 64 x 256 x 36 packed-FMA block ----
#pragma unroll 4
        for (int kk = 0; kk < KC; kk++) {
            const ulonglong2* pa = (const ulonglong2*)&sA[kk * MT + tm * 8];
            ulonglong2 a01 = pa[0];           // m-pairs 0,1 (broadcast in warp)
            ulonglong2 a23 = pa[1];           // m-pairs 2,3
            float4 b0 = *(const float4*)&sB[kk * SB_STRIDE + tn4];
            float4 b1 = *(const float4*)&sB[kk * SB_STRIDE + 128 + tn4];
            float bs[8] = {b0.x, b0.y, b0.z, b0.w, b1.x, b1.y, b1.z, b1.w};
#pragma unroll
            for (int n = 0; n < 8; n++) {
                unsigned long long bd = dup2(bs[n]);
                fma2(acc_[n][0], a01.x, bd);
                fma2(acc_[n][1], a01.y, bd);
                fma2(acc_[n][2], a23.x, bd);
                fma2(acc_[n][3], a23.y, bd);
            }
        }
        __syncthreads();
    }

    // ---- epilogue: 8 consecutive hw per (thread, n) -> 2x STG.128 ----
    const int hw0 = (p0 & 4095) + tm * 8;
    float* ob = out + (size_t)b * OPL * HWS;
#pragma unroll
    for (int g = 0; g < 2; g++) {
#pragma unroll
        for (int j = 0; j < 4; j++) {
            int n  = g * 128 + tn4 + j;
            int ai = g * 4 + j;
            UPair u0, u1, u2, u3;
            u0.u = acc_[ai][0]; u1.u = acc_[ai][1];
            u2.u = acc_[ai][2]; u3.u = acc_[ai][3];
            float4 v0 = make_float4(u0.f.x, u0.f.y, u1.f.x, u1.f.y);
            float4 v1 = make_float4(u2.f.x, u2.f.y, u3.f.x, u3.f.y);
            *(float4*)&ob[(size_t)n * HWS + hw0]     = v0;
            *(float4*)&ob[(size_t)n * HWS + hw0 + 4] = v1;
        }
    }
}

// ---------------------------------------------------------------------------
extern "C" void kernel_launch(void* const* d_in, const int* in_sizes, int n_in,
                              void* d_out, int out_size)
{
    const float* x      = (const float*)d_in[0];   // (4,256,64,64)
    const float* w_p    = (const float*)d_in[1];   // (18,256,3,3)
    const float* w_conv = (const float*)d_in[2];   // (256,256,3,3)
    float* out = (float*)d_out;                    // (4,256,64,64)

    const int smem2 = (KC * MT + KC * SB_STRIDE + MT * NP * 8) * 4;  // 65,088 B
    cudaFuncSetAttribute(main_kernel, cudaFuncAttributeMaxDynamicSharedMemorySize, smem2);

    transpose_w<<<(KTOT * OPL + 255) / 256, 256>>>(w_conv);
    offsets_kernel<<<128, 128>>>(x, w_p);
    main_kernel<<<BB * HWS / MT, NTH, smem2>>>(x, out);
}

// round 4
// speedup vs baseline: 1.0874x; 1.0312x over previous
#include <cuda_runtime.h>

#define BB   4
#define CC   256
#define HH   64
#define WW   64
#define HWS  4096         // H*W
#define NP   9            // kernel points
#define OCH  18           // offset channels
#define OPL  256          // out planes
#define KTOT 2304         // C*9

#define MT   64           // GEMM M tile (positions per block) == one image row
#define CCK  4            // channels per K chunk
#define KC   36           // K per chunk = CCK*9
#define NTH  288          // 9 warps: 576 (k,posl) pairs = 2 per thread
#define SB_STRIDE 260     // padded B row stride (floats)

// sampling metadata scratch: per (b,h,w,k): 4 bilinear weights + 4 flat gather indices
__device__ float4 g_mw[BB * HWS * NP];
__device__ int4   g_mi[BB * HWS * NP];
// transposed conv weights: g_wT[kg][o], kg = c*9+k  (2.36 MB, L2-resident)
__device__ float  g_wT[KTOT * OPL];

// ---------------------------------------------------------------------------
// packed fp32 helpers (FFMA2 path — PTX-only)
// ---------------------------------------------------------------------------
__device__ __forceinline__ unsigned long long dup2(float v) {
    unsigned long long r;
    asm("mov.b64 %0, {%1, %1};" : "=l"(r) : "f"(v));
    return r;
}
__device__ __forceinline__ void fma2(unsigned long long& acc,
                                     unsigned long long a, unsigned long long b) {
    asm("fma.rn.f32x2 %0, %1, %2, %0;" : "+l"(acc) : "l"(a), "l"(b));
}
union UPair { unsigned long long u; float2 f; };

// ---------------------------------------------------------------------------
// Kernel 0: transpose w_conv [o][kg] -> g_wT [kg][o]
// ---------------------------------------------------------------------------
__global__ __launch_bounds__(256) void transpose_w(const float* __restrict__ wc)
{
    int idx = blockIdx.x * 256 + threadIdx.x;
    if (idx < KTOT * OPL) {
        int kg = idx >> 8;
        int o  = idx & 255;
        g_wT[idx] = wc[o * KTOT + kg];
    }
}

// ---------------------------------------------------------------------------
// Kernel 1: offset conv (3x3, pad 1, C=256 -> 18) + sampling metadata
// ---------------------------------------------------------------------------
__global__ __launch_bounds__(128) void offsets_kernel(const float* __restrict__ x,
                                                      const float* __restrict__ w_p)
{
    __shared__ float s_wp[32][OCH][12];

    const int tid = threadIdx.x;
    const int pos = blockIdx.x * 128 + tid;
    const int b = pos >> 12;
    const int h = (pos >> 6) & 63;
    const int w = pos & 63;

    float acc[OCH];
#pragma unroll
    for (int i = 0; i < OCH; i++) acc[i] = 0.f;

    const float* xb = x + (size_t)b * CC * HWS;

    for (int c0 = 0; c0 < CC; c0 += 32) {
        __syncthreads();
        for (int i = tid; i < 32 * OCH * 9; i += 128) {
            int cl = i / (OCH * 9);
            int r  = i % (OCH * 9);
            int o  = r / 9;
            int t  = r % 9;
            s_wp[cl][o][t] = w_p[(o * CC + c0 + cl) * 9 + t];
        }
        __syncthreads();

        for (int cl = 0; cl < 32; cl++) {
            const float* xp = xb + (c0 + cl) * HWS;
            float xv[9];
#pragma unroll
            for (int dh = -1; dh <= 1; dh++) {
#pragma unroll
                for (int dw = -1; dw <= 1; dw++) {
                    int hh = h + dh, ww = w + dw;
                    float v = 0.f;
                    if (hh >= 0 && hh < HH && ww >= 0 && ww < WW) v = xp[hh * WW + ww];
                    xv[(dh + 1) * 3 + (dw + 1)] = v;
                }
            }
#pragma unroll
            for (int o = 0; o < OCH; o++) {
                float4 wa = *(const float4*)&s_wp[cl][o][0];
                float4 wb = *(const float4*)&s_wp[cl][o][4];
                float  w8 = s_wp[cl][o][8];
                acc[o] += wa.x * xv[0] + wa.y * xv[1] + wa.z * xv[2] + wa.w * xv[3]
                        + wb.x * xv[4] + wb.y * xv[5] + wb.z * xv[6] + wb.w * xv[7]
                        + w8  * xv[8];
            }
        }
    }

#pragma unroll
    for (int k = 0; k < 9; k++) {
        float rx = (float)(k / 3 - 1);
        float ry = (float)(k % 3 - 1);
        float px = acc[k]     + rx + (float)(h + 1);
        float py = acc[9 + k] + ry + (float)(w + 1);
        float fx = floorf(px), fy = floorf(py);
        float ltx = fminf(fmaxf(fx,        0.f), 63.f);
        float lty = fminf(fmaxf(fy,        0.f), 63.f);
        float rbx = fminf(fmaxf(fx + 1.f,  0.f), 63.f);
        float rby = fminf(fmaxf(fy + 1.f,  0.f), 63.f);
        float pxc = fminf(fmaxf(px,        0.f), 63.f);
        float pyc = fminf(fmaxf(py,        0.f), 63.f);
        float glt = (1.f + (ltx - pxc)) * (1.f + (lty - pyc));
        float grb = (1.f - (rbx - pxc)) * (1.f - (rby - pyc));
        float glb = (1.f + (ltx - pxc)) * (1.f - (rby - pyc));
        float grt = (1.f - (rbx - pxc)) * (1.f + (lty - pyc));
        int iltx = (int)ltx, ilty = (int)lty, irbx = (int)rbx, irby = (int)rby;
        g_mw[pos * 9 + k] = make_float4(glt, grb, glb, grt);
        g_mi[pos * 9 + k] = make_int4(iltx * WW + ilty,
                                      irbx * WW + irby,
                                      iltx * WW + irby,
                                      irbx * WW + ilty);
    }
}

// ---------------------------------------------------------------------------
// Kernel 2: implicit gather-GEMM, packed-fp32 (FFMA2)
//   288 threads: each owns 2 (k,posl) metadata pairs in REGISTERS for the
//   whole kernel; gather loops channels inside -> 32 independent LDGs/chunk.
//   Math: warps 0-7 do 8m x 8n packed outer product. 2 CTAs/SM overlap.
// ---------------------------------------------------------------------------
__global__ void __launch_bounds__(NTH, 2) main_kernel(const float* __restrict__ x,
                                                      float* __restrict__ out)
{
    __shared__ float sA[KC * MT];          //  9,216 B
    __shared__ float sB[KC * SB_STRIDE];   // 37,440 B   (total 46.7 KB/CTA)

    const int tid = threadIdx.x;
    const int p0  = blockIdx.x * MT;  // all positions in one batch b, one row h
    const int b   = p0 >> 12;
    const float* xb = x + (size_t)b * CC * HWS;

    // ---- per-thread sampling metadata: 2 pairs, register-resident ----
    const int pA = tid, pB = tid + NTH;          // pair ids in [0,576)
    const int kA = pA >> 6, plA = pA & 63;
    const int kB = pB >> 6, plB = pB & 63;
    const float4 mwA = g_mw[(p0 + plA) * NP + kA];
    const int4   miA = g_mi[(p0 + plA) * NP + kA];
    const float4 mwB = g_mw[(p0 + plB) * NP + kB];
    const int4   miB = g_mi[(p0 + plB) * NP + kB];
    const int sAoffA = kA * MT + plA;            // sA[(cl*9+kA)*MT + plA]
    const int sAoffB = kB * MT + plB;

    // math-phase ids (warps 0..7 only)
    const int tn4 = (tid & 31) * 4;
    const int tm  = (tid >> 5) & 7;
    const bool mathw = (tid < 256);

    unsigned long long acc_[8][4];
#pragma unroll
    for (int n = 0; n < 8; n++)
#pragma unroll
        for (int mp = 0; mp < 4; mp++) acc_[n][mp] = 0ull;

    for (int c0 = 0; c0 < CC; c0 += CCK) {
        // ---- stage A: 8 bilinear samples/thread, meta from regs ----
        const float* xc = xb + c0 * HWS;
#pragma unroll
        for (int cl = 0; cl < CCK; cl++) {
            const float* xp = xc + cl * HWS;
            float vA = mwA.x * __ldg(xp + miA.x) + mwA.y * __ldg(xp + miA.y)
                     + mwA.z * __ldg(xp + miA.z) + mwA.w * __ldg(xp + miA.w);
            float vB = mwB.x * __ldg(xp + miB.x) + mwB.y * __ldg(xp + miB.y)
                     + mwB.z * __ldg(xp + miB.z) + mwB.w * __ldg(xp + miB.w);
            sA[cl * (9 * MT) + sAoffA] = vA;
            sA[cl * (9 * MT) + sAoffB] = vB;
        }
        // ---- stage B: 36x256 weight chunk, 8 float4/thread, coalesced ----
#pragma unroll
        for (int r = 0; r < 8; r++) {
            int i  = tid + r * NTH;               // 0..2303
            int kk = i >> 6;
            int o4 = (i & 63) << 2;
            *(float4*)&sB[kk * SB_STRIDE + o4] =
                *(const float4*)&g_wT[(c0 * 9 + kk) * OPL + o4];
        }
        __syncthreads();

        // ---- 64 x 256 x 36 packed-FMA block (warps 0-7) ----
        if (mathw) {
#pragma unroll 6
            for (int kk = 0; kk < KC; kk++) {
                const ulonglong2* pa = (const ulonglong2*)&sA[kk * MT + tm * 8];
                ulonglong2 a01 = pa[0];
                ulonglong2 a23 = pa[1];
                float4 b0 = *(const float4*)&sB[kk * SB_STRIDE + tn4];
                float4 b1 = *(const float4*)&sB[kk * SB_STRIDE + 128 + tn4];
                float bs[8] = {b0.x, b0.y, b0.z, b0.w, b1.x, b1.y, b1.z, b1.w};
#pragma unroll
                for (int n = 0; n < 8; n++) {
                    unsigned long long bd = dup2(bs[n]);
                    fma2(acc_[n][0], a01.x, bd);
                    fma2(acc_[n][1], a01.y, bd);
                    fma2(acc_[n][2], a23.x, bd);
                    fma2(acc_[n][3], a23.y, bd);
                }
            }
        }
        __syncthreads();
    }

    // ---- epilogue: 8 consecutive hw per (thread, n) -> 2x STG.128 ----
    if (mathw) {
        const int hw0 = (p0 & 4095) + tm * 8;
        float* ob = out + (size_t)b * OPL * HWS;
#pragma unroll
        for (int g = 0; g < 2; g++) {
#pragma unroll
            for (int j = 0; j < 4; j++) {
                int n  = g * 128 + tn4 + j;
                int ai = g * 4 + j;
                UPair u0, u1, u2, u3;
                u0.u = acc_[ai][0]; u1.u = acc_[ai][1];
                u2.u = acc_[ai][2]; u3.u = acc_[ai][3];
                float4 v0 = make_float4(u0.f.x, u0.f.y, u1.f.x, u1.f.y);
                float4 v1 = make_float4(u2.f.x, u2.f.y, u3.f.x, u3.f.y);
                *(float4*)&ob[(size_t)n * HWS + hw0]     = v0;
                *(float4*)&ob[(size_t)n * HWS + hw0 + 4] = v1;
            }
        }
    }
}

// ---------------------------------------------------------------------------
extern "C" void kernel_launch(void* const* d_in, const int* in_sizes, int n_in,
                              void* d_out, int out_size)
{
    const float* x      = (const float*)d_in[0];   // (4,256,64,64)
    const float* w_p    = (const float*)d_in[1];   // (18,256,3,3)
    const float* w_conv = (const float*)d_in[2];   // (256,256,3,3)
    float* out = (float*)d_out;                    // (4,256,64,64)

    transpose_w<<<(KTOT * OPL + 255) / 256, 256>>>(w_conv);
    offsets_kernel<<<128, 128>>>(x, w_p);
    main_kernel<<<BB * HWS / MT, NTH>>>(x, out);
}